// round 2
// baseline (speedup 1.0000x reference)
#include <cuda_runtime.h>
#include <math.h>

#define BS 128
#define T_STEPS 32
#define DIN 128
#define DH 128
#define NS 512
#define NTHR 512
#define NWARP (NTHR/32)
#define EPS 1e-8f

// Scratch: per-batch memory matrix and (h,r) history for the final output GEMM.
__device__ float g_mem[(size_t)BS * NS * DH];          // 33.5 MB, L2-resident
__device__ float g_hr[(size_t)BS * T_STEPS * 2 * DH];  // 4 MB

__device__ __forceinline__ float softplusf_(float x) {
    return x > 20.f ? x : log1pf(expf(x));
}
__device__ __forceinline__ float sigmoidf_(float x) {
    return 1.f / (1.f + expf(-x));
}
__device__ __forceinline__ float wredsum(float v) {
#pragma unroll
    for (int o = 16; o; o >>= 1) v += __shfl_xor_sync(0xffffffffu, v, o);
    return v;
}
__device__ __forceinline__ float wredmax(float v) {
#pragma unroll
    for (int o = 16; o; o >>= 1) v = fmaxf(v, __shfl_xor_sync(0xffffffffu, v, o));
    return v;
}

__device__ __forceinline__ float block_sum(float v, float* s_red, int tid) {
    v = wredsum(v);
    __syncthreads();  // protect s_red reuse across consecutive reductions
    if ((tid & 31) == 0) s_red[tid >> 5] = v;
    __syncthreads();
    float t = 0.f;
#pragma unroll
    for (int i = 0; i < NWARP; i++) t += s_red[i];
    return t;
}
__device__ __forceinline__ float block_max(float v, float* s_red, int tid) {
    v = wredmax(v);
    __syncthreads();
    if ((tid & 31) == 0) s_red[tid >> 5] = v;
    __syncthreads();
    float t = -1e30f;
#pragma unroll
    for (int i = 0; i < NWARP; i++) t = fmaxf(t, s_red[i]);
    return t;
}

// One attention head: scores -> softmax -> interpolate -> shift -> sharpen -> normalize.
// 512 threads, one slot per thread (NTHR == NS).
__device__ __forceinline__ void attn_head(
    const float* __restrict__ dot, const float* __restrict__ nrm,
    const float* __restrict__ wprev, float* wtmp, float* wout,
    float beta, float g, float s0, float s1, float s2,
    float gamma, float knorm, int tid, float* s_red)
{
    const int n = tid;
    float sc = beta * dot[n] / (nrm[n] * knorm + EPS);
    float mx = block_max(sc, s_red, tid);
    float ev = expf(sc - mx);
    float tot = block_sum(ev, s_red, tid);
    float wc = ev / tot;
    float wg = g * wc + (1.f - g) * wprev[n];
    wtmp[n] = wg;
    __syncthreads();
    // roll(w,-1)[n] = w[n+1]; roll(w,+1)[n] = w[n-1]
    float wt = s0 * wtmp[(n + 1) & (NS - 1)] + s1 * wg + s2 * wtmp[(n - 1) & (NS - 1)];
    float w = powf(wt, gamma);
    float sw = block_sum(w, s_red, tid);
    wout[n] = w / (sw + EPS);
    __syncthreads();
}

__global__ void __launch_bounds__(NTHR) ntm_kernel(
    const float* __restrict__ x,
    const float* __restrict__ Wxh, const float* __restrict__ Whh,
    const float* __restrict__ Wrh, const float* __restrict__ bh,
    const float* __restrict__ Wr, const float* __restrict__ br,
    const float* __restrict__ Ww, const float* __restrict__ bw)
{
    __shared__ float s_xh[T_STEPS * DH];    // x@Wxh + bh, precomputed for all t
    __shared__ float s_h[DH], s_r[DH];
    __shared__ float s_o[524];              // [o_r(134) | o_w(390)]
    __shared__ float s_dotr[NS], s_dotw[NS], s_norm[NS];
    __shared__ float s_wprev[NS], s_wtmp[NS], s_wr[NS], s_ww[NS];
    __shared__ float s_part[NWARP * DH];    // matvec partials / r reduction
    __shared__ float s_red[NWARP];
    __shared__ float s_scal[2];             // ||k_r||, ||k_w||

    const int tid = threadIdx.x;
    const int wid = tid >> 5, lane = tid & 31;
    const int b = blockIdx.x;

    // ---- init mem = 1e-6 (per-batch slice; deterministic every call) ----
    {
        float4* mb = reinterpret_cast<float4*>(g_mem + (size_t)b * NS * DH);
        float4 iv = make_float4(1e-6f, 1e-6f, 1e-6f, 1e-6f);
        for (int i = tid; i < NS * DH / 4; i += NTHR) mb[i] = iv;
    }

    // ---- precompute xh[t][j] = x_t @ Wxh + bh ----
    {
        const float* xb = x + (size_t)b * T_STEPS * DIN;
        for (int idx = tid; idx < T_STEPS * DH; idx += NTHR) {
            int t = idx >> 7, j = idx & 127;
            float acc = bh[j];
            const float* xr = xb + t * DIN;
#pragma unroll 4
            for (int k = 0; k < DIN; k++) acc = fmaf(xr[k], Wxh[k * DH + j], acc);
            s_xh[idx] = acc;
        }
    }
    if (tid < DH) { s_h[tid] = 0.f; s_r[tid] = 0.f; }
    s_wprev[tid] = 1.f / NS;
    __syncthreads();

    const float4* memq = reinterpret_cast<const float4*>(g_mem + (size_t)b * NS * DH);
    float4* memq_w = reinterpret_cast<float4*>(g_mem + (size_t)b * NS * DH);

    for (int t = 0; t < T_STEPS; t++) {
        // ---- h = tanh(xh_t + h@Whh + r@Wrh) : 4 quarter-partials ----
        {
            int q = tid >> 7, j = tid & 127;
            const float* W = (q < 2) ? Whh : Wrh;
            const float* v = (q < 2) ? s_h : s_r;
            int k0 = (q & 1) * 64;
            float acc = 0.f;
#pragma unroll 8
            for (int k = 0; k < 64; k++) acc = fmaf(v[k0 + k], W[(k0 + k) * DH + j], acc);
            s_part[q * DH + j] = acc;
            __syncthreads();
            if (tid < DH) {
                float hv = s_xh[t * DH + tid] + s_part[tid] + s_part[DH + tid]
                         + s_part[2 * DH + tid] + s_part[3 * DH + tid];
                s_h[tid] = tanhf(hv);
            }
            __syncthreads();
        }

        // ---- o = h @ [Wr | Ww] + [br | bw] ----
        for (int c = tid; c < 524; c += NTHR) {
            const float* W; int ld, cc; float bias;
            if (c < 134) { W = Wr; ld = 134; cc = c; bias = br[c]; }
            else         { W = Ww; ld = 390; cc = c - 134; bias = bw[c - 134]; }
            float acc = bias;
#pragma unroll 4
            for (int k = 0; k < DH; k++) acc = fmaf(s_h[k], W[k * ld + cc], acc);
            s_o[c] = acc;
        }
        __syncthreads();

        // ---- in-place e = sigmoid, a = tanh; key norms ----
        if (tid < DH) {
            s_o[268 + tid] = sigmoidf_(s_o[268 + tid]);
            s_o[396 + tid] = tanhf(s_o[396 + tid]);
        }
        if (wid == 14) {
            float v = 0.f;
            for (int i = lane; i < DH; i += 32) { float u = s_o[i]; v = fmaf(u, u, v); }
            v = wredsum(v);
            if (!lane) s_scal[0] = sqrtf(v);
        }
        if (wid == 15) {
            float v = 0.f;
            for (int i = lane; i < DH; i += 32) { float u = s_o[134 + i]; v = fmaf(u, u, v); }
            v = wredsum(v);
            if (!lane) s_scal[1] = sqrtf(v);
        }
        __syncthreads();

        // ---- pass A over mem: dot_r, dot_w, ||mem_n|| in ONE read ----
        {
            float kr0 = s_o[lane * 4 + 0], kr1 = s_o[lane * 4 + 1];
            float kr2 = s_o[lane * 4 + 2], kr3 = s_o[lane * 4 + 3];
            float kw0 = s_o[134 + lane * 4 + 0], kw1 = s_o[134 + lane * 4 + 1];
            float kw2 = s_o[134 + lane * 4 + 2], kw3 = s_o[134 + lane * 4 + 3];
            for (int i = 0; i < 32; i += 2) {
                int n = wid * 32 + i;
                float4 v0 = memq[n * 32 + lane];
                float4 v1 = memq[(n + 1) * 32 + lane];
                float dr0 = v0.x * kr0 + v0.y * kr1 + v0.z * kr2 + v0.w * kr3;
                float dw0 = v0.x * kw0 + v0.y * kw1 + v0.z * kw2 + v0.w * kw3;
                float nm0 = v0.x * v0.x + v0.y * v0.y + v0.z * v0.z + v0.w * v0.w;
                float dr1 = v1.x * kr0 + v1.y * kr1 + v1.z * kr2 + v1.w * kr3;
                float dw1 = v1.x * kw0 + v1.y * kw1 + v1.z * kw2 + v1.w * kw3;
                float nm1 = v1.x * v1.x + v1.y * v1.y + v1.z * v1.z + v1.w * v1.w;
                dr0 = wredsum(dr0); dw0 = wredsum(dw0); nm0 = wredsum(nm0);
                dr1 = wredsum(dr1); dw1 = wredsum(dw1); nm1 = wredsum(nm1);
                if (!lane) {
                    s_dotr[n] = dr0; s_dotw[n] = dw0; s_norm[n] = sqrtf(nm0);
                    s_dotr[n + 1] = dr1; s_dotw[n + 1] = dw1; s_norm[n + 1] = sqrtf(nm1);
                }
            }
            __syncthreads();
        }

        // ---- scalars (computed redundantly per thread, cheap) ----
        float beta_r = softplusf_(s_o[128]);
        float g_r = sigmoidf_(s_o[129]);
        float gamma_r = 1.f + softplusf_(s_o[133]);
        float sr0, sr1, sr2;
        {
            float q0 = s_o[130], q1 = s_o[131], q2 = s_o[132];
            float qm = fmaxf(q0, fmaxf(q1, q2));
            float e0 = expf(q0 - qm), e1 = expf(q1 - qm), e2 = expf(q2 - qm);
            float qs = e0 + e1 + e2;
            sr0 = e0 / qs; sr1 = e1 / qs; sr2 = e2 / qs;
        }
        float beta_w = softplusf_(s_o[134 + 128]);
        float g_w = sigmoidf_(s_o[134 + 129]);
        float gamma_w = 1.f + softplusf_(s_o[134 + 133]);
        float sw0, sw1, sw2;
        {
            float q0 = s_o[134 + 130], q1 = s_o[134 + 131], q2 = s_o[134 + 132];
            float qm = fmaxf(q0, fmaxf(q1, q2));
            float e0 = expf(q0 - qm), e1 = expf(q1 - qm), e2 = expf(q2 - qm);
            float qs = e0 + e1 + e2;
            sw0 = e0 / qs; sw1 = e1 / qs; sw2 = e2 / qs;
        }
        float knr = s_scal[0], knw = s_scal[1];

        // read head uses w_prev; write head uses freshly computed w_r
        attn_head(s_dotr, s_norm, s_wprev, s_wtmp, s_wr,
                  beta_r, g_r, sr0, sr1, sr2, gamma_r, knr, tid, s_red);
        attn_head(s_dotw, s_norm, s_wr, s_wtmp, s_ww,
                  beta_w, g_w, sw0, sw1, sw2, gamma_w, knw, tid, s_red);

        // ---- pass B over mem: r = w_r @ mem  +  erase/add update, fused ----
        {
            float ee0 = s_o[268 + lane * 4 + 0], ee1 = s_o[268 + lane * 4 + 1];
            float ee2 = s_o[268 + lane * 4 + 2], ee3 = s_o[268 + lane * 4 + 3];
            float aa0 = s_o[396 + lane * 4 + 0], aa1 = s_o[396 + lane * 4 + 1];
            float aa2 = s_o[396 + lane * 4 + 2], aa3 = s_o[396 + lane * 4 + 3];
            float ac0 = 0.f, ac1 = 0.f, ac2 = 0.f, ac3 = 0.f;
            for (int i = 0; i < 32; i++) {
                int n = wid * 32 + i;
                float wr = s_wr[n], ww = s_ww[n];
                float4 v = memq[n * 32 + lane];
                ac0 = fmaf(wr, v.x, ac0);
                ac1 = fmaf(wr, v.y, ac1);
                ac2 = fmaf(wr, v.z, ac2);
                ac3 = fmaf(wr, v.w, ac3);
                v.x = v.x * (1.f - ww * ee0) + ww * aa0;
                v.y = v.y * (1.f - ww * ee1) + ww * aa1;
                v.z = v.z * (1.f - ww * ee2) + ww * aa2;
                v.w = v.w * (1.f - ww * ee3) + ww * aa3;
                memq_w[n * 32 + lane] = v;
            }
            s_part[wid * DH + lane * 4 + 0] = ac0;
            s_part[wid * DH + lane * 4 + 1] = ac1;
            s_part[wid * DH + lane * 4 + 2] = ac2;
            s_part[wid * DH + lane * 4 + 3] = ac3;
            __syncthreads();
            if (tid < DH) {
                float rv = 0.f;
#pragma unroll
                for (int w2 = 0; w2 < NWARP; w2++) rv += s_part[w2 * DH + tid];
                s_r[tid] = rv;
            }
            __syncthreads();
        }

        // ---- store (h, r) history for the final output GEMM ----
        {
            size_t row = (size_t)(b * T_STEPS + t);
            if (tid < 2 * DH)
                g_hr[row * 2 * DH + tid] = (tid < DH) ? s_h[tid] : s_r[tid - DH];
        }

        // ---- carry: w_prev <- w_w ----
        s_wprev[tid] = s_ww[tid];
        __syncthreads();
    }
}

// Y = [H | R] @ Wout + bout over all (b, t) rows at once.
__global__ void __launch_bounds__(256) out_gemm(
    const float* __restrict__ Wout, const float* __restrict__ bout,
    float* __restrict__ out)
{
    __shared__ float As[32][256];
    const int tid = threadIdx.x, lane = tid & 31, wid = tid >> 5;
    const int rbase = blockIdx.x * 32;

    for (int idx = tid; idx < 32 * 256; idx += 256) {
        int r = idx >> 8, k = idx & 255;
        As[r][k] = g_hr[(size_t)(rbase + r) * 256 + k];
    }
    __syncthreads();

    float acc[4][4];
#pragma unroll
    for (int i = 0; i < 4; i++)
#pragma unroll
        for (int j = 0; j < 4; j++) acc[i][j] = 0.f;

    const int c0 = lane * 4;
    const int r0 = wid * 4;
    for (int k = 0; k < 256; k++) {
        float4 wv = *reinterpret_cast<const float4*>(Wout + k * 128 + c0);
#pragma unroll
        for (int i = 0; i < 4; i++) {
            float av = As[r0 + i][k];
            acc[i][0] = fmaf(av, wv.x, acc[i][0]);
            acc[i][1] = fmaf(av, wv.y, acc[i][1]);
            acc[i][2] = fmaf(av, wv.z, acc[i][2]);
            acc[i][3] = fmaf(av, wv.w, acc[i][3]);
        }
    }
    float4 bo = *reinterpret_cast<const float4*>(bout + c0);
#pragma unroll
    for (int i = 0; i < 4; i++) {
        float4 o4 = make_float4(acc[i][0] + bo.x, acc[i][1] + bo.y,
                                acc[i][2] + bo.z, acc[i][3] + bo.w);
        *reinterpret_cast<float4*>(out + (size_t)(rbase + r0 + i) * 128 + c0) = o4;
    }
}

extern "C" void kernel_launch(void* const* d_in, const int* in_sizes, int n_in,
                              void* d_out, int out_size)
{
    const float* x    = (const float*)d_in[0];
    const float* Wxh  = (const float*)d_in[1];
    const float* Whh  = (const float*)d_in[2];
    const float* Wrh  = (const float*)d_in[3];
    const float* bh   = (const float*)d_in[4];
    const float* Wout = (const float*)d_in[5];
    const float* bout = (const float*)d_in[6];
    const float* Wr   = (const float*)d_in[7];
    const float* br   = (const float*)d_in[8];
    const float* Ww   = (const float*)d_in[9];
    const float* bw   = (const float*)d_in[10];
    float* out = (float*)d_out;

    ntm_kernel<<<BS, NTHR>>>(x, Wxh, Whh, Wrh, bh, Wr, br, Ww, bw);
    out_gemm<<<BS * T_STEPS / 32, 256>>>(Wout, bout, out);
}

// round 3
// speedup vs baseline: 1.0019x; 1.0019x over previous
#include <cuda_runtime.h>
#include <math.h>

#define BS 128
#define T_STEPS 32
#define DIN 128
#define DH 128
#define NS 512
#define NTHR 512
#define NWARP (NTHR/32)
#define EPS 1e-8f

// Scratch: per-batch memory matrix and (h,r) history for the final output GEMM.
__device__ float g_mem[(size_t)BS * NS * DH];          // 33.5 MB, L2-resident
__device__ float g_hr[(size_t)BS * T_STEPS * 2 * DH];  // 4 MB

__device__ __forceinline__ float softplusf_(float x) {
    return x > 20.f ? x : log1pf(expf(x));
}
__device__ __forceinline__ float sigmoidf_(float x) {
    return 1.f / (1.f + expf(-x));
}
__device__ __forceinline__ float wredsum(float v) {
#pragma unroll
    for (int o = 16; o; o >>= 1) v += __shfl_xor_sync(0xffffffffu, v, o);
    return v;
}
__device__ __forceinline__ float wredmax(float v) {
#pragma unroll
    for (int o = 16; o; o >>= 1) v = fmaxf(v, __shfl_xor_sync(0xffffffffu, v, o));
    return v;
}

__device__ __forceinline__ float block_sum(float v, float* s_red, int tid) {
    v = wredsum(v);
    __syncthreads();  // protect s_red reuse across consecutive reductions
    if ((tid & 31) == 0) s_red[tid >> 5] = v;
    __syncthreads();
    float t = 0.f;
#pragma unroll
    for (int i = 0; i < NWARP; i++) t += s_red[i];
    return t;
}
__device__ __forceinline__ float block_max(float v, float* s_red, int tid) {
    v = wredmax(v);
    __syncthreads();
    if ((tid & 31) == 0) s_red[tid >> 5] = v;
    __syncthreads();
    float t = -1e30f;
#pragma unroll
    for (int i = 0; i < NWARP; i++) t = fmaxf(t, s_red[i]);
    return t;
}

// One attention head: scores -> softmax -> interpolate -> shift -> sharpen -> normalize.
// 512 threads, one slot per thread (NTHR == NS).
__device__ __forceinline__ void attn_head(
    const float* __restrict__ dot, const float* __restrict__ nrm,
    const float* __restrict__ wprev, float* wtmp, float* wout,
    float beta, float g, float s0, float s1, float s2,
    float gamma, float knorm, int tid, float* s_red)
{
    const int n = tid;
    float sc = beta * dot[n] / (nrm[n] * knorm + EPS);
    float mx = block_max(sc, s_red, tid);
    float ev = expf(sc - mx);
    float tot = block_sum(ev, s_red, tid);
    float wc = ev / tot;
    float wg = g * wc + (1.f - g) * wprev[n];
    wtmp[n] = wg;
    __syncthreads();
    // roll(w,-1)[n] = w[n+1]; roll(w,+1)[n] = w[n-1]
    float wt = s0 * wtmp[(n + 1) & (NS - 1)] + s1 * wg + s2 * wtmp[(n - 1) & (NS - 1)];
    float w = powf(wt, gamma);
    float sw = block_sum(w, s_red, tid);
    wout[n] = w / (sw + EPS);
    __syncthreads();
}

__global__ void __launch_bounds__(NTHR) ntm_kernel(
    const float* __restrict__ x,
    const float* __restrict__ Wxh, const float* __restrict__ Whh,
    const float* __restrict__ Wrh, const float* __restrict__ bh,
    const float* __restrict__ Wr, const float* __restrict__ br,
    const float* __restrict__ Ww, const float* __restrict__ bw)
{
    __shared__ float s_xh[T_STEPS * DH];    // x@Wxh + bh, precomputed for all t
    __shared__ float s_h[DH], s_r[DH];
    __shared__ float s_o[524];              // [o_r(134) | o_w(390)]
    __shared__ float s_dotr[NS], s_dotw[NS], s_norm[NS];
    __shared__ float s_wprev[NS], s_wtmp[NS], s_wr[NS], s_ww[NS];
    __shared__ float s_part[NWARP * DH];    // matvec partials / r reduction
    __shared__ float s_red[NWARP];
    __shared__ float s_scal[2];             // ||k_r||, ||k_w||

    const int tid = threadIdx.x;
    const int wid = tid >> 5, lane = tid & 31;
    const int b = blockIdx.x;

    // ---- init mem = 1e-6 (per-batch slice; deterministic every call) ----
    {
        float4* mb = reinterpret_cast<float4*>(g_mem + (size_t)b * NS * DH);
        float4 iv = make_float4(1e-6f, 1e-6f, 1e-6f, 1e-6f);
        for (int i = tid; i < NS * DH / 4; i += NTHR) mb[i] = iv;
    }

    // ---- precompute xh[t][j] = x_t @ Wxh + bh ----
    {
        const float* xb = x + (size_t)b * T_STEPS * DIN;
        for (int idx = tid; idx < T_STEPS * DH; idx += NTHR) {
            int t = idx >> 7, j = idx & 127;
            float acc = bh[j];
            const float* xr = xb + t * DIN;
#pragma unroll 4
            for (int k = 0; k < DIN; k++) acc = fmaf(xr[k], Wxh[k * DH + j], acc);
            s_xh[idx] = acc;
        }
    }
    if (tid < DH) { s_h[tid] = 0.f; s_r[tid] = 0.f; }
    s_wprev[tid] = 1.f / NS;
    __syncthreads();

    const float4* memq = reinterpret_cast<const float4*>(g_mem + (size_t)b * NS * DH);
    float4* memq_w = reinterpret_cast<float4*>(g_mem + (size_t)b * NS * DH);

    for (int t = 0; t < T_STEPS; t++) {
        // ---- h = tanh(xh_t + h@Whh + r@Wrh) : 4 quarter-partials ----
        {
            int q = tid >> 7, j = tid & 127;
            const float* W = (q < 2) ? Whh : Wrh;
            const float* v = (q < 2) ? s_h : s_r;
            int k0 = (q & 1) * 64;
            float acc = 0.f;
#pragma unroll 8
            for (int k = 0; k < 64; k++) acc = fmaf(v[k0 + k], W[(k0 + k) * DH + j], acc);
            s_part[q * DH + j] = acc;
            __syncthreads();
            if (tid < DH) {
                float hv = s_xh[t * DH + tid] + s_part[tid] + s_part[DH + tid]
                         + s_part[2 * DH + tid] + s_part[3 * DH + tid];
                s_h[tid] = tanhf(hv);
            }
            __syncthreads();
        }

        // ---- o = h @ [Wr | Ww] + [br | bw] ----
        for (int c = tid; c < 524; c += NTHR) {
            const float* W; int ld, cc; float bias;
            if (c < 134) { W = Wr; ld = 134; cc = c; bias = br[c]; }
            else         { W = Ww; ld = 390; cc = c - 134; bias = bw[c - 134]; }
            float acc = bias;
#pragma unroll 4
            for (int k = 0; k < DH; k++) acc = fmaf(s_h[k], W[k * ld + cc], acc);
            s_o[c] = acc;
        }
        __syncthreads();

        // ---- in-place e = sigmoid, a = tanh; key norms ----
        if (tid < DH) {
            s_o[268 + tid] = sigmoidf_(s_o[268 + tid]);
            s_o[396 + tid] = tanhf(s_o[396 + tid]);
        }
        if (wid == 14) {
            float v = 0.f;
            for (int i = lane; i < DH; i += 32) { float u = s_o[i]; v = fmaf(u, u, v); }
            v = wredsum(v);
            if (!lane) s_scal[0] = sqrtf(v);
        }
        if (wid == 15) {
            float v = 0.f;
            for (int i = lane; i < DH; i += 32) { float u = s_o[134 + i]; v = fmaf(u, u, v); }
            v = wredsum(v);
            if (!lane) s_scal[1] = sqrtf(v);
        }
        __syncthreads();

        // ---- pass A over mem: dot_r, dot_w, ||mem_n|| in ONE read ----
        {
            float kr0 = s_o[lane * 4 + 0], kr1 = s_o[lane * 4 + 1];
            float kr2 = s_o[lane * 4 + 2], kr3 = s_o[lane * 4 + 3];
            float kw0 = s_o[134 + lane * 4 + 0], kw1 = s_o[134 + lane * 4 + 1];
            float kw2 = s_o[134 + lane * 4 + 2], kw3 = s_o[134 + lane * 4 + 3];
            for (int i = 0; i < 32; i += 2) {
                int n = wid * 32 + i;
                float4 v0 = memq[n * 32 + lane];
                float4 v1 = memq[(n + 1) * 32 + lane];
                float dr0 = v0.x * kr0 + v0.y * kr1 + v0.z * kr2 + v0.w * kr3;
                float dw0 = v0.x * kw0 + v0.y * kw1 + v0.z * kw2 + v0.w * kw3;
                float nm0 = v0.x * v0.x + v0.y * v0.y + v0.z * v0.z + v0.w * v0.w;
                float dr1 = v1.x * kr0 + v1.y * kr1 + v1.z * kr2 + v1.w * kr3;
                float dw1 = v1.x * kw0 + v1.y * kw1 + v1.z * kw2 + v1.w * kw3;
                float nm1 = v1.x * v1.x + v1.y * v1.y + v1.z * v1.z + v1.w * v1.w;
                dr0 = wredsum(dr0); dw0 = wredsum(dw0); nm0 = wredsum(nm0);
                dr1 = wredsum(dr1); dw1 = wredsum(dw1); nm1 = wredsum(nm1);
                if (!lane) {
                    s_dotr[n] = dr0; s_dotw[n] = dw0; s_norm[n] = sqrtf(nm0);
                    s_dotr[n + 1] = dr1; s_dotw[n + 1] = dw1; s_norm[n + 1] = sqrtf(nm1);
                }
            }
            __syncthreads();
        }

        // ---- scalars (computed redundantly per thread, cheap) ----
        float beta_r = softplusf_(s_o[128]);
        float g_r = sigmoidf_(s_o[129]);
        float gamma_r = 1.f + softplusf_(s_o[133]);
        float sr0, sr1, sr2;
        {
            float q0 = s_o[130], q1 = s_o[131], q2 = s_o[132];
            float qm = fmaxf(q0, fmaxf(q1, q2));
            float e0 = expf(q0 - qm), e1 = expf(q1 - qm), e2 = expf(q2 - qm);
            float qs = e0 + e1 + e2;
            sr0 = e0 / qs; sr1 = e1 / qs; sr2 = e2 / qs;
        }
        float beta_w = softplusf_(s_o[134 + 128]);
        float g_w = sigmoidf_(s_o[134 + 129]);
        float gamma_w = 1.f + softplusf_(s_o[134 + 133]);
        float sw0, sw1, sw2;
        {
            float q0 = s_o[134 + 130], q1 = s_o[134 + 131], q2 = s_o[134 + 132];
            float qm = fmaxf(q0, fmaxf(q1, q2));
            float e0 = expf(q0 - qm), e1 = expf(q1 - qm), e2 = expf(q2 - qm);
            float qs = e0 + e1 + e2;
            sw0 = e0 / qs; sw1 = e1 / qs; sw2 = e2 / qs;
        }
        float knr = s_scal[0], knw = s_scal[1];

        // read head uses w_prev; write head uses freshly computed w_r
        attn_head(s_dotr, s_norm, s_wprev, s_wtmp, s_wr,
                  beta_r, g_r, sr0, sr1, sr2, gamma_r, knr, tid, s_red);
        attn_head(s_dotw, s_norm, s_wr, s_wtmp, s_ww,
                  beta_w, g_w, sw0, sw1, sw2, gamma_w, knw, tid, s_red);

        // ---- pass B over mem: r = w_r @ mem  +  erase/add update, fused ----
        {
            float ee0 = s_o[268 + lane * 4 + 0], ee1 = s_o[268 + lane * 4 + 1];
            float ee2 = s_o[268 + lane * 4 + 2], ee3 = s_o[268 + lane * 4 + 3];
            float aa0 = s_o[396 + lane * 4 + 0], aa1 = s_o[396 + lane * 4 + 1];
            float aa2 = s_o[396 + lane * 4 + 2], aa3 = s_o[396 + lane * 4 + 3];
            float ac0 = 0.f, ac1 = 0.f, ac2 = 0.f, ac3 = 0.f;
            for (int i = 0; i < 32; i++) {
                int n = wid * 32 + i;
                float wr = s_wr[n], ww = s_ww[n];
                float4 v = memq[n * 32 + lane];
                ac0 = fmaf(wr, v.x, ac0);
                ac1 = fmaf(wr, v.y, ac1);
                ac2 = fmaf(wr, v.z, ac2);
                ac3 = fmaf(wr, v.w, ac3);
                v.x = v.x * (1.f - ww * ee0) + ww * aa0;
                v.y = v.y * (1.f - ww * ee1) + ww * aa1;
                v.z = v.z * (1.f - ww * ee2) + ww * aa2;
                v.w = v.w * (1.f - ww * ee3) + ww * aa3;
                memq_w[n * 32 + lane] = v;
            }
            s_part[wid * DH + lane * 4 + 0] = ac0;
            s_part[wid * DH + lane * 4 + 1] = ac1;
            s_part[wid * DH + lane * 4 + 2] = ac2;
            s_part[wid * DH + lane * 4 + 3] = ac3;
            __syncthreads();
            if (tid < DH) {
                float rv = 0.f;
#pragma unroll
                for (int w2 = 0; w2 < NWARP; w2++) rv += s_part[w2 * DH + tid];
                s_r[tid] = rv;
            }
            __syncthreads();
        }

        // ---- store (h, r) history for the final output GEMM ----
        {
            size_t row = (size_t)(b * T_STEPS + t);
            if (tid < 2 * DH)
                g_hr[row * 2 * DH + tid] = (tid < DH) ? s_h[tid] : s_r[tid - DH];
        }

        // ---- carry: w_prev <- w_w ----
        s_wprev[tid] = s_ww[tid];
        __syncthreads();
    }
}

// Y = [H | R] @ Wout + bout over all (b, t) rows at once.
__global__ void __launch_bounds__(256) out_gemm(
    const float* __restrict__ Wout, const float* __restrict__ bout,
    float* __restrict__ out)
{
    __shared__ float As[32][256];
    const int tid = threadIdx.x, lane = tid & 31, wid = tid >> 5;
    const int rbase = blockIdx.x * 32;

    for (int idx = tid; idx < 32 * 256; idx += 256) {
        int r = idx >> 8, k = idx & 255;
        As[r][k] = g_hr[(size_t)(rbase + r) * 256 + k];
    }
    __syncthreads();

    float acc[4][4];
#pragma unroll
    for (int i = 0; i < 4; i++)
#pragma unroll
        for (int j = 0; j < 4; j++) acc[i][j] = 0.f;

    const int c0 = lane * 4;
    const int r0 = wid * 4;
    for (int k = 0; k < 256; k++) {
        float4 wv = *reinterpret_cast<const float4*>(Wout + k * 128 + c0);
#pragma unroll
        for (int i = 0; i < 4; i++) {
            float av = As[r0 + i][k];
            acc[i][0] = fmaf(av, wv.x, acc[i][0]);
            acc[i][1] = fmaf(av, wv.y, acc[i][1]);
            acc[i][2] = fmaf(av, wv.z, acc[i][2]);
            acc[i][3] = fmaf(av, wv.w, acc[i][3]);
        }
    }
    float4 bo = *reinterpret_cast<const float4*>(bout + c0);
#pragma unroll
    for (int i = 0; i < 4; i++) {
        float4 o4 = make_float4(acc[i][0] + bo.x, acc[i][1] + bo.y,
                                acc[i][2] + bo.z, acc[i][3] + bo.w);
        *reinterpret_cast<float4*>(out + (size_t)(rbase + r0 + i) * 128 + c0) = o4;
    }
}

extern "C" void kernel_launch(void* const* d_in, const int* in_sizes, int n_in,
                              void* d_out, int out_size)
{
    const float* x    = (const float*)d_in[0];
    const float* Wxh  = (const float*)d_in[1];
    const float* Whh  = (const float*)d_in[2];
    const float* Wrh  = (const float*)d_in[3];
    const float* bh   = (const float*)d_in[4];
    const float* Wout = (const float*)d_in[5];
    const float* bout = (const float*)d_in[6];
    const float* Wr   = (const float*)d_in[7];
    const float* br   = (const float*)d_in[8];
    const float* Ww   = (const float*)d_in[9];
    const float* bw   = (const float*)d_in[10];
    float* out = (float*)d_out;

    ntm_kernel<<<BS, NTHR>>>(x, Wxh, Whh, Wrh, bh, Wr, br, Ww, bw);
    out_gemm<<<BS * T_STEPS / 32, 256>>>(Wout, bout, out);
}

// round 4
// speedup vs baseline: 1.6775x; 1.6742x over previous
#include <cuda_runtime.h>
#include <math.h>

#define BS 128
#define T_STEPS 32
#define DIN 128
#define DH 128
#define NS 512
#define NTHR 512
#define NWARP (NTHR/32)
#define EPS 1e-8f

// Scratch in device globals (allocation-free rule).
// g_mem layout is TRANSPOSED: g_mem[b][m][n]  (feature-major, m=0..127, n=0..511)
__device__ float g_mem[(size_t)BS * DH * NS];          // 33.5 MB, L2-resident
__device__ float g_hr[(size_t)BS * T_STEPS * 2 * DH];  // 4 MB (h,r) history
__device__ float g_xh[(size_t)BS * T_STEPS * DH];      // 2 MB precomputed x@Wxh+bh

// ---- shared memory layout (floats) ----
#define OFF_WHH   0                      // 16384
#define OFF_WRH   (OFF_WHH + 16384)      // 16384
#define OFF_WR    (OFF_WRH + 16384)      // 17152  (128 x 134)
#define OFF_BIAS  (OFF_WR  + 17152)      // 524    (br | bw)
#define OFF_O     (OFF_BIAS + 524)       // 524    (o_r | o_w)
#define OFF_KK    (OFF_O   + 524)        // 256    float2[128]: (k_r[m], k_w[m])
#define OFF_EA    (OFF_KK  + 256)        // 256    float2[128]: (e[m], a[m])
#define OFF_H     (OFF_EA  + 256)        // 128
#define OFF_R     (OFF_H   + 128)        // 128
#define OFF_PART  (OFF_R   + 128)        // 512
#define OFF_WPRE  (OFF_PART + 512)       // 512
#define OFF_WRW   (OFF_WPRE + 512)       // 512    w_r
#define OFF_WWW   (OFF_WRW + 512)        // 512    w_w
#define OFF_WTMP  (OFF_WWW + 512)        // 512
#define OFF_RED   (OFF_WTMP + 512)       // 16
#define OFF_SCAL  (OFF_RED + 16)         // 2
#define SMEM_FLOATS (OFF_SCAL + 2)       // 54314 floats = 217256 B

__device__ __forceinline__ float softplusf_(float x) {
    return x > 20.f ? x : log1pf(expf(x));
}
__device__ __forceinline__ float sigmoidf_(float x) {
    return 1.f / (1.f + expf(-x));
}
__device__ __forceinline__ float wredsum(float v) {
#pragma unroll
    for (int o = 16; o; o >>= 1) v += __shfl_xor_sync(0xffffffffu, v, o);
    return v;
}
__device__ __forceinline__ float wredmax(float v) {
#pragma unroll
    for (int o = 16; o; o >>= 1) v = fmaxf(v, __shfl_xor_sync(0xffffffffu, v, o));
    return v;
}
__device__ __forceinline__ float block_sum(float v, float* s_red, int tid) {
    v = wredsum(v);
    __syncthreads();
    if ((tid & 31) == 0) s_red[tid >> 5] = v;
    __syncthreads();
    float t = 0.f;
#pragma unroll
    for (int i = 0; i < NWARP; i++) t += s_red[i];
    return t;
}
__device__ __forceinline__ float block_max(float v, float* s_red, int tid) {
    v = wredmax(v);
    __syncthreads();
    if ((tid & 31) == 0) s_red[tid >> 5] = v;
    __syncthreads();
    float t = -1e30f;
#pragma unroll
    for (int i = 0; i < NWARP; i++) t = fmaxf(t, s_red[i]);
    return t;
}

// One attention head. Score `sc` arrives in a register (per-thread slot).
__device__ __forceinline__ void attn_head(
    float sc, const float* __restrict__ wprev, float* wtmp, float* wout,
    float g, float s0, float s1, float s2, float gamma,
    int tid, float* s_red)
{
    float mx = block_max(sc, s_red, tid);
    float ev = expf(sc - mx);
    float tot = block_sum(ev, s_red, tid);
    float wc = ev / tot;
    float wg = g * wc + (1.f - g) * wprev[tid];
    wtmp[tid] = wg;
    __syncthreads();
    // roll(w,-1)[n] = w[n+1]; roll(w,+1)[n] = w[n-1]
    float wt = s0 * wtmp[(tid + 1) & (NS - 1)] + s1 * wg + s2 * wtmp[(tid - 1) & (NS - 1)];
    float w = powf(wt, gamma);
    float sw = block_sum(w, s_red, tid);
    wout[tid] = w / (sw + EPS);
    __syncthreads();
}

__global__ void __launch_bounds__(NTHR) ntm_kernel(
    const float* __restrict__ x,
    const float* __restrict__ Wxh, const float* __restrict__ Whh,
    const float* __restrict__ Wrh, const float* __restrict__ bh,
    const float* __restrict__ Wr, const float* __restrict__ br,
    const float* __restrict__ Ww, const float* __restrict__ bw)
{
    extern __shared__ float sm[];
    float* s_Whh = sm + OFF_WHH;
    float* s_Wrh = sm + OFF_WRH;
    float* s_Wr  = sm + OFF_WR;
    float* s_bias= sm + OFF_BIAS;
    float* s_o   = sm + OFF_O;
    float2* s_kk = (float2*)(sm + OFF_KK);
    float2* s_ea = (float2*)(sm + OFF_EA);
    float* s_h   = sm + OFF_H;
    float* s_r   = sm + OFF_R;
    float* s_part= sm + OFF_PART;
    float* s_wpre= sm + OFF_WPRE;
    float* s_wr  = sm + OFF_WRW;
    float* s_ww  = sm + OFF_WWW;
    float* s_wtmp= sm + OFF_WTMP;
    float* s_red = sm + OFF_RED;
    float* s_scal= sm + OFF_SCAL;

    const int tid = threadIdx.x;
    const int wid = tid >> 5, lane = tid & 31;
    const int b = blockIdx.x;

    // ---- stage in-loop weights + biases into smem (once) ----
    for (int i = tid; i < 16384; i += NTHR) s_Whh[i] = Whh[i];
    for (int i = tid; i < 16384; i += NTHR) s_Wrh[i] = Wrh[i];
    for (int i = tid; i < 17152; i += NTHR) s_Wr[i]  = Wr[i];
    for (int i = tid; i < 524;   i += NTHR) s_bias[i] = (i < 134) ? br[i] : bw[i - 134];

    // ---- init mem = 1e-6 (transposed layout; values uniform so layout moot) ----
    {
        float4* mb = reinterpret_cast<float4*>(g_mem + (size_t)b * NS * DH);
        float4 iv = make_float4(1e-6f, 1e-6f, 1e-6f, 1e-6f);
        for (int i = tid; i < NS * DH / 4; i += NTHR) mb[i] = iv;
    }

    // ---- precompute xh[t][j] = x_t @ Wxh + bh into global scratch ----
    {
        const float* xb = x + (size_t)b * T_STEPS * DIN;
        for (int idx = tid; idx < T_STEPS * DH; idx += NTHR) {
            int t = idx >> 7, j = idx & 127;
            float acc = bh[j];
            const float* xr = xb + t * DIN;
#pragma unroll 4
            for (int k = 0; k < DIN; k++) acc = fmaf(xr[k], Wxh[k * DH + j], acc);
            g_xh[(size_t)b * T_STEPS * DH + idx] = acc;
        }
    }
    if (tid < DH) { s_h[tid] = 0.f; s_r[tid] = 0.f; }
    s_wpre[tid] = 1.f / NS;
    __syncthreads();

    float* mT = g_mem + (size_t)b * DH * NS;   // mT[m*NS + n]

    for (int t = 0; t < T_STEPS; t++) {
        // ---- h = tanh(xh_t + h@Whh + r@Wrh), weights from smem ----
        {
            int q = tid >> 7, j = tid & 127;
            const float* W = (q < 2) ? s_Whh : s_Wrh;
            const float* v = (q < 2) ? s_h : s_r;
            int k0 = (q & 1) * 64;
            float acc = 0.f;
#pragma unroll 8
            for (int k = 0; k < 64; k++) acc = fmaf(v[k0 + k], W[(k0 + k) * DH + j], acc);
            s_part[q * DH + j] = acc;
            __syncthreads();
            if (tid < DH) {
                float hv = g_xh[(size_t)b * T_STEPS * DH + t * DH + tid]
                         + s_part[tid] + s_part[DH + tid]
                         + s_part[2 * DH + tid] + s_part[3 * DH + tid];
                s_h[tid] = tanhf(hv);
            }
            __syncthreads();
        }

        // ---- o = h @ [Wr | Ww] + bias (Wr from smem, Ww streamed from L2) ----
        for (int c = tid; c < 524; c += NTHR) {
            float acc = s_bias[c];
            if (c < 134) {
#pragma unroll 8
                for (int k = 0; k < DH; k++) acc = fmaf(s_h[k], s_Wr[k * 134 + c], acc);
            } else {
                int cc = c - 134;
#pragma unroll 8
                for (int k = 0; k < DH; k++) acc = fmaf(s_h[k], Ww[k * 390 + cc], acc);
            }
            s_o[c] = acc;
        }
        __syncthreads();

        // ---- build packed keys (k_r,k_w), (e,a); key norms ----
        if (tid < 128) {
            s_kk[tid] = make_float2(s_o[tid], s_o[134 + tid]);
        } else if (tid < 256) {
            int m = tid - 128;
            s_ea[m] = make_float2(sigmoidf_(s_o[268 + m]), tanhf(s_o[396 + m]));
        }
        if (wid == 14) {
            float v = 0.f;
            for (int i = lane; i < DH; i += 32) { float u = s_o[i]; v = fmaf(u, u, v); }
            v = wredsum(v);
            if (!lane) s_scal[0] = sqrtf(v);
        }
        if (wid == 15) {
            float v = 0.f;
            for (int i = lane; i < DH; i += 32) { float u = s_o[134 + i]; v = fmaf(u, u, v); }
            v = wredsum(v);
            if (!lane) s_scal[1] = sqrtf(v);
        }
        __syncthreads();

        // ---- pass A: thread-per-slot dots + norm, fully local (no shuffles) ----
        float dr = 0.f, dw = 0.f, nm = 0.f;
        {
            const float4* kk4 = (const float4*)s_kk;
#pragma unroll 8
            for (int m = 0; m < DH; m += 2) {
                float v0 = mT[m * NS + tid];
                float v1 = mT[(m + 1) * NS + tid];
                float4 k4 = kk4[m >> 1];       // {kr[m], kw[m], kr[m+1], kw[m+1]}
                dr = fmaf(v0, k4.x, dr); dw = fmaf(v0, k4.y, dw); nm = fmaf(v0, v0, nm);
                dr = fmaf(v1, k4.z, dr); dw = fmaf(v1, k4.w, dw); nm = fmaf(v1, v1, nm);
            }
        }
        float nrm = sqrtf(nm);

        // ---- head scalars (redundant per thread, cheap) ----
        float beta_r = softplusf_(s_o[128]);
        float g_r = sigmoidf_(s_o[129]);
        float gamma_r = 1.f + softplusf_(s_o[133]);
        float sr0, sr1, sr2;
        {
            float q0 = s_o[130], q1 = s_o[131], q2 = s_o[132];
            float qm = fmaxf(q0, fmaxf(q1, q2));
            float e0 = expf(q0 - qm), e1 = expf(q1 - qm), e2 = expf(q2 - qm);
            float qs = e0 + e1 + e2;
            sr0 = e0 / qs; sr1 = e1 / qs; sr2 = e2 / qs;
        }
        float beta_w = softplusf_(s_o[262]);
        float g_w = sigmoidf_(s_o[263]);
        float gamma_w = 1.f + softplusf_(s_o[267]);
        float sw0, sw1, sw2;
        {
            float q0 = s_o[264], q1 = s_o[265], q2 = s_o[266];
            float qm = fmaxf(q0, fmaxf(q1, q2));
            float e0 = expf(q0 - qm), e1 = expf(q1 - qm), e2 = expf(q2 - qm);
            float qs = e0 + e1 + e2;
            sw0 = e0 / qs; sw1 = e1 / qs; sw2 = e2 / qs;
        }
        float sc_r = beta_r * dr / (nrm * s_scal[0] + EPS);
        float sc_w = beta_w * dw / (nrm * s_scal[1] + EPS);

        attn_head(sc_r, s_wpre, s_wtmp, s_wr,
                  g_r, sr0, sr1, sr2, gamma_r, tid, s_red);
        attn_head(sc_w, s_wr, s_wtmp, s_ww,
                  g_w, sw0, sw1, sw2, gamma_w, tid, s_red);

        // ---- pass B: warp-per-feature-row; fused read-vector + erase/add ----
        {
            float4 wr4[4], ww4[4];
            const float4* wrv = (const float4*)s_wr;
            const float4* wwv = (const float4*)s_ww;
#pragma unroll
            for (int c = 0; c < 4; c++) { wr4[c] = wrv[c * 32 + lane]; ww4[c] = wwv[c * 32 + lane]; }
#pragma unroll 2
            for (int mi = 0; mi < 8; mi++) {
                int m = wid * 8 + mi;
                float2 ea = s_ea[m];
                float4* rp = (float4*)(mT + (size_t)m * NS);
                float racc = 0.f;
#pragma unroll
                for (int c = 0; c < 4; c++) {
                    float4 v = rp[c * 32 + lane];
                    racc = fmaf(wr4[c].x, v.x, racc);
                    racc = fmaf(wr4[c].y, v.y, racc);
                    racc = fmaf(wr4[c].z, v.z, racc);
                    racc = fmaf(wr4[c].w, v.w, racc);
                    v.x = v.x * (1.f - ww4[c].x * ea.x) + ww4[c].x * ea.y;
                    v.y = v.y * (1.f - ww4[c].y * ea.x) + ww4[c].y * ea.y;
                    v.z = v.z * (1.f - ww4[c].z * ea.x) + ww4[c].z * ea.y;
                    v.w = v.w * (1.f - ww4[c].w * ea.x) + ww4[c].w * ea.y;
                    rp[c * 32 + lane] = v;
                }
                racc = wredsum(racc);
                if (!lane) s_r[m] = racc;
            }
            __syncthreads();
        }

        // ---- store (h, r) history for the final output GEMM ----
        if (tid < 2 * DH) {
            size_t row = (size_t)(b * T_STEPS + t);
            g_hr[row * 2 * DH + tid] = (tid < DH) ? s_h[tid] : s_r[tid - DH];
        }

        // ---- carry: w_prev <- w_w ----
        s_wpre[tid] = s_ww[tid];
        __syncthreads();
    }
}

// Y = [H | R] @ Wout + bout ; Wout fully staged in smem.
#define OUT_SMEM_FLOATS (32768 + 8192)
__global__ void __launch_bounds__(256) out_gemm(
    const float* __restrict__ Wout, const float* __restrict__ bout,
    float* __restrict__ out)
{
    extern __shared__ float sh[];
    float* shW = sh;            // 256 x 128
    float* As  = sh + 32768;    // 32 x 256
    const int tid = threadIdx.x, lane = tid & 31, wid = tid >> 5;
    const int rbase = blockIdx.x * 32;

    {
        float4* dst = (float4*)shW;
        const float4* src = (const float4*)Wout;
        for (int i = tid; i < 8192; i += 256) dst[i] = src[i];
        float4* dA = (float4*)As;
        const float4* sA = (const float4*)(g_hr + (size_t)rbase * 256);
        for (int i = tid; i < 2048; i += 256) dA[i] = sA[i];
    }
    __syncthreads();

    float acc[4][4];
#pragma unroll
    for (int i = 0; i < 4; i++)
#pragma unroll
        for (int j = 0; j < 4; j++) acc[i][j] = 0.f;

    const int c0 = lane * 4;
    const int r0 = wid * 4;
#pragma unroll 4
    for (int k = 0; k < 256; k++) {
        float4 wv = ((const float4*)shW)[k * 32 + lane];
#pragma unroll
        for (int i = 0; i < 4; i++) {
            float av = As[(r0 + i) * 256 + k];
            acc[i][0] = fmaf(av, wv.x, acc[i][0]);
            acc[i][1] = fmaf(av, wv.y, acc[i][1]);
            acc[i][2] = fmaf(av, wv.z, acc[i][2]);
            acc[i][3] = fmaf(av, wv.w, acc[i][3]);
        }
    }
    float4 bo = *reinterpret_cast<const float4*>(bout + c0);
#pragma unroll
    for (int i = 0; i < 4; i++) {
        float4 o4 = make_float4(acc[i][0] + bo.x, acc[i][1] + bo.y,
                                acc[i][2] + bo.z, acc[i][3] + bo.w);
        *reinterpret_cast<float4*>(out + (size_t)(rbase + r0 + i) * 128 + c0) = o4;
    }
}

extern "C" void kernel_launch(void* const* d_in, const int* in_sizes, int n_in,
                              void* d_out, int out_size)
{
    const float* x    = (const float*)d_in[0];
    const float* Wxh  = (const float*)d_in[1];
    const float* Whh  = (const float*)d_in[2];
    const float* Wrh  = (const float*)d_in[3];
    const float* bh   = (const float*)d_in[4];
    const float* Wout = (const float*)d_in[5];
    const float* bout = (const float*)d_in[6];
    const float* Wr   = (const float*)d_in[7];
    const float* br   = (const float*)d_in[8];
    const float* Ww   = (const float*)d_in[9];
    const float* bw   = (const float*)d_in[10];
    float* out = (float*)d_out;

    cudaFuncSetAttribute(ntm_kernel, cudaFuncAttributeMaxDynamicSharedMemorySize,
                         SMEM_FLOATS * sizeof(float));
    cudaFuncSetAttribute(out_gemm, cudaFuncAttributeMaxDynamicSharedMemorySize,
                         OUT_SMEM_FLOATS * sizeof(float));

    ntm_kernel<<<BS, NTHR, SMEM_FLOATS * sizeof(float)>>>(
        x, Wxh, Whh, Wrh, bh, Wr, br, Ww, bw);
    out_gemm<<<BS * T_STEPS / 32, 256, OUT_SMEM_FLOATS * sizeof(float)>>>(
        Wout, bout, out);
}

// round 5
// speedup vs baseline: 2.0613x; 1.2288x over previous
#include <cuda_runtime.h>
#include <math.h>

#define BS 128
#define T_STEPS 32
#define DIN 128
#define DH 128
#define NS 512
#define NTHR 512
#define NWARP (NTHR/32)
#define EPS 1e-8f

typedef unsigned long long ull;

// Global scratch (allocation-free rule). Upper half of mem: features 64..127.
__device__ float g_memU[(size_t)BS * 64 * NS];         // 16.8 MB
__device__ float g_hr[(size_t)BS * T_STEPS * 2 * DH];  // 4 MB (h,r) history
__device__ float g_xh[(size_t)BS * T_STEPS * DH];      // 2 MB x@Wxh+bh

// ---- shared memory layout (float offsets) ----
#define OFF_MEM   0                      // 32768 : mem rows 0..63 [m][n]
#define OFF_WHH   (OFF_MEM  + 32768)     // 16384
#define OFF_KP    (OFF_WHH  + 16384)     // 256  float4[64]: {kr[m],kr[m+64],kw[m],kw[m+64]}
#define OFF_EA    (OFF_KP   + 256)       // 256  float2[128]: (e[m], a[m])
#define OFF_BIAS  (OFF_EA   + 256)       // 524
#define OFF_O     (OFF_BIAS + 524)       // 524
#define OFF_H     (OFF_O    + 524)       // 128
#define OFF_R     (OFF_H    + 128)       // 128
#define OFF_PART  (OFF_R    + 128)       // 1088
#define OFF_WPRE  (OFF_PART + 1088)      // 512
#define OFF_WRW   (OFF_WPRE + 512)       // 512
#define OFF_WWW   (OFF_WRW  + 512)       // 512
#define OFF_WTMP  (OFF_WWW  + 512)       // 512
#define OFF_RED   (OFF_WTMP + 512)       // 16
#define OFF_SCAL  (OFF_RED  + 16)        // 2
#define SMEM_FLOATS (OFF_SCAL + 2)       // 54122 floats = 216488 B

// ---- f32x2 packed-FMA helpers (FFMA2 — PTX-only path) ----
__device__ __forceinline__ ull pack2(float lo, float hi) {
    ull r; asm("mov.b64 %0, {%1, %2};" : "=l"(r) : "f"(lo), "f"(hi)); return r;
}
__device__ __forceinline__ float2 unpack2(ull v) {
    float2 r; asm("mov.b64 {%0, %1}, %2;" : "=f"(r.x), "=f"(r.y) : "l"(v)); return r;
}
__device__ __forceinline__ ull ffma2(ull a, ull b, ull c) {
    ull d; asm("fma.rn.f32x2 %0, %1, %2, %3;" : "=l"(d) : "l"(a), "l"(b), "l"(c)); return d;
}
__device__ __forceinline__ ull fmul2(ull a, ull b) {
    ull d; asm("mul.rn.f32x2 %0, %1, %2;" : "=l"(d) : "l"(a), "l"(b)); return d;
}

__device__ __forceinline__ float softplusf_(float x) {
    return x > 20.f ? x : log1pf(expf(x));
}
__device__ __forceinline__ float sigmoidf_(float x) {
    return 1.f / (1.f + expf(-x));
}
__device__ __forceinline__ float wredsum(float v) {
#pragma unroll
    for (int o = 16; o; o >>= 1) v += __shfl_xor_sync(0xffffffffu, v, o);
    return v;
}
__device__ __forceinline__ float block_sum(float v, float* s_red, int tid) {
    v = wredsum(v);
    __syncthreads();
    if ((tid & 31) == 0) s_red[tid >> 5] = v;
    __syncthreads();
    float t = 0.f;
#pragma unroll
    for (int i = 0; i < NWARP; i++) t += s_red[i];
    return t;
}

// Attention head, no max-subtraction (scores bounded; fp32-safe).
__device__ __forceinline__ void attn_head(
    float sc, const float* __restrict__ wprev, float* wtmp, float* wout,
    float g, float s0, float s1, float s2, float gamma,
    int tid, float* s_red)
{
    float ev = __expf(sc);
    float tot = block_sum(ev, s_red, tid);
    float wc = ev / tot;
    float wg = g * wc + (1.f - g) * wprev[tid];
    wtmp[tid] = wg;
    __syncthreads();
    float wt = s0 * wtmp[(tid + 1) & (NS - 1)] + s1 * wg + s2 * wtmp[(tid - 1) & (NS - 1)];
    float w = __powf(wt, gamma);
    float sw = block_sum(w, s_red, tid);
    wout[tid] = w / (sw + EPS);
    __syncthreads();
}

__global__ void dummy_k() {}

__global__ void __launch_bounds__(NTHR) ntm_kernel(
    const float* __restrict__ x,
    const float* __restrict__ Wxh, const float* __restrict__ Whh,
    const float* __restrict__ Wrh, const float* __restrict__ bh,
    const float* __restrict__ Wr, const float* __restrict__ br,
    const float* __restrict__ Ww, const float* __restrict__ bw)
{
    extern __shared__ float sm[];
    float*  s_mem = sm + OFF_MEM;
    float*  s_Whh = sm + OFF_WHH;
    float4* s_kp  = (float4*)(sm + OFF_KP);
    float2* s_ea  = (float2*)(sm + OFF_EA);
    float*  s_bias= sm + OFF_BIAS;
    float*  s_o   = sm + OFF_O;
    float*  s_h   = sm + OFF_H;
    float*  s_r   = sm + OFF_R;
    float*  s_part= sm + OFF_PART;
    float*  s_wpre= sm + OFF_WPRE;
    float*  s_wr  = sm + OFF_WRW;
    float*  s_ww  = sm + OFF_WWW;
    float*  s_wtmp= sm + OFF_WTMP;
    float*  s_red = sm + OFF_RED;
    float*  s_scal= sm + OFF_SCAL;

    const int tid = threadIdx.x;
    const int wid = tid >> 5, lane = tid & 31;
    const int b = blockIdx.x;

    // ---- stage Whh + biases into smem ----
    for (int i = tid; i < 16384; i += NTHR) s_Whh[i] = Whh[i];
    for (int i = tid; i < 524;   i += NTHR) s_bias[i] = (i < 134) ? br[i] : bw[i - 134];

    // ---- init mem = 1e-6 : lower 64 rows in smem, upper 64 rows global ----
    {
        float4 iv = make_float4(1e-6f, 1e-6f, 1e-6f, 1e-6f);
        float4* mb = reinterpret_cast<float4*>(s_mem);
        for (int i = tid; i < 64 * NS / 4; i += NTHR) mb[i] = iv;
        float4* gu = reinterpret_cast<float4*>(g_memU + (size_t)b * 64 * NS);
        for (int i = tid; i < 64 * NS / 4; i += NTHR) gu[i] = iv;
    }

    // ---- precompute xh[t][j] = x_t @ Wxh + bh ----
    {
        const float* xb = x + (size_t)b * T_STEPS * DIN;
        for (int idx = tid; idx < T_STEPS * DH; idx += NTHR) {
            int t = idx >> 7, j = idx & 127;
            float acc = bh[j];
            const float* xr = xb + t * DIN;
#pragma unroll 8
            for (int k = 0; k < DIN; k++) acc = fmaf(xr[k], Wxh[k * DH + j], acc);
            g_xh[(size_t)b * T_STEPS * DH + idx] = acc;
        }
    }
    if (tid < DH) { s_h[tid] = 0.f; s_r[tid] = 0.f; }
    s_wpre[tid] = 1.f / NS;
    __syncthreads();

    float* mU = g_memU + (size_t)b * 64 * NS;   // upper rows: mU[(m-64)*NS + n]
    const unsigned kp_base = (unsigned)__cvta_generic_to_shared(s_kp);

    for (int t = 0; t < T_STEPS; t++) {
        // ======== h = tanh(xh_t + h@Whh + r@Wrh) ========
        {
            int q = tid >> 7, j = tid & 127;
            float acc = 0.f;
            if (q < 2) {
                int k0 = q * 64;
#pragma unroll 16
                for (int k = 0; k < 64; k++)
                    acc = fmaf(s_h[k0 + k], s_Whh[(k0 + k) * DH + j], acc);
            } else {
                int k0 = (q - 2) * 64;
#pragma unroll 16
                for (int k = 0; k < 64; k++)
                    acc = fmaf(s_r[k0 + k], Wrh[(k0 + k) * DH + j], acc);
            }
            s_part[q * DH + j] = acc;
            __syncthreads();
            if (tid < DH) {
                float hv = g_xh[(size_t)b * T_STEPS * DH + t * DH + tid]
                         + s_part[tid] + s_part[DH + tid]
                         + s_part[2 * DH + tid] + s_part[3 * DH + tid];
                s_h[tid] = tanhf(hv);
            }
            __syncthreads();
        }

        // ======== o = h @ [Wr | Ww] + bias, k-split x2 for MLP ========
        for (int task = tid; task < 1048; task += NTHR) {
            int hh = task / 524;
            int c = task - hh * 524;
            int k0 = hh * 64;
            const float* Wp; int ld, cc;
            if (c < 134) { Wp = Wr; ld = 134; cc = c; }
            else         { Wp = Ww; ld = 390; cc = c - 134; }
            float acc = 0.f;
#pragma unroll 16
            for (int k = 0; k < 64; k++)
                acc = fmaf(s_h[k0 + k], Wp[(k0 + k) * ld + cc], acc);
            s_part[task] = acc;
        }
        __syncthreads();
        for (int c = tid; c < 524; c += NTHR)
            s_o[c] = s_bias[c] + s_part[c] + s_part[524 + c];
        __syncthreads();

        // ======== packed keys, (e,a), key norms ========
        if (tid < 64) {
            s_kp[tid] = make_float4(s_o[tid], s_o[tid + 64],
                                    s_o[134 + tid], s_o[134 + tid + 64]);
        } else if (tid < 192) {
            int m = tid - 64;
            s_ea[m] = make_float2(sigmoidf_(s_o[268 + m]), tanhf(s_o[396 + m]));
        }
        if (wid == 14) {
            float v = 0.f;
            for (int i = lane; i < DH; i += 32) { float u = s_o[i]; v = fmaf(u, u, v); }
            v = wredsum(v);
            if (!lane) s_scal[0] = sqrtf(v);
        }
        if (wid == 15) {
            float v = 0.f;
            for (int i = lane; i < DH; i += 32) { float u = s_o[134 + i]; v = fmaf(u, u, v); }
            v = wredsum(v);
            if (!lane) s_scal[1] = sqrtf(v);
        }
        __syncthreads();

        // ======== pass A: thread-per-slot, packed {smem row m, global row m+64} ========
        ull drP = 0ull, dwP = 0ull, nmP = 0ull;   // bit pattern {0.f,0.f}
#pragma unroll 8
        for (int m = 0; m < 64; m++) {
            float v0 = s_mem[m * NS + tid];
            float u0 = mU[m * NS + tid];
            ull vv = pack2(v0, u0);
            ull kr2, kw2;
            asm("ld.shared.v2.b64 {%0, %1}, [%2];"
                : "=l"(kr2), "=l"(kw2) : "r"(kp_base + m * 16));
            drP = ffma2(vv, kr2, drP);
            dwP = ffma2(vv, kw2, dwP);
            nmP = ffma2(vv, vv, nmP);
        }
        float2 drp = unpack2(drP), dwp = unpack2(dwP), nmp = unpack2(nmP);
        float dr = drp.x + drp.y, dw = dwp.x + dwp.y;
        float nrm = sqrtf(nmp.x + nmp.y);

        // ======== head scalars ========
        float beta_r = softplusf_(s_o[128]);
        float g_r = sigmoidf_(s_o[129]);
        float gamma_r = 1.f + softplusf_(s_o[133]);
        float sr0, sr1, sr2;
        {
            float q0 = s_o[130], q1 = s_o[131], q2 = s_o[132];
            float qm = fmaxf(q0, fmaxf(q1, q2));
            float e0 = expf(q0 - qm), e1 = expf(q1 - qm), e2 = expf(q2 - qm);
            float qs = e0 + e1 + e2;
            sr0 = e0 / qs; sr1 = e1 / qs; sr2 = e2 / qs;
        }
        float beta_w = softplusf_(s_o[262]);
        float g_w = sigmoidf_(s_o[263]);
        float gamma_w = 1.f + softplusf_(s_o[267]);
        float sw0, sw1, sw2;
        {
            float q0 = s_o[264], q1 = s_o[265], q2 = s_o[266];
            float qm = fmaxf(q0, fmaxf(q1, q2));
            float e0 = expf(q0 - qm), e1 = expf(q1 - qm), e2 = expf(q2 - qm);
            float qs = e0 + e1 + e2;
            sw0 = e0 / qs; sw1 = e1 / qs; sw2 = e2 / qs;
        }
        float sc_r = beta_r * dr / (nrm * s_scal[0] + EPS);
        float sc_w = beta_w * dw / (nrm * s_scal[1] + EPS);

        attn_head(sc_r, s_wpre, s_wtmp, s_wr,
                  g_r, sr0, sr1, sr2, gamma_r, tid, s_red);
        attn_head(sc_w, s_wr, s_wtmp, s_ww,
                  g_w, sw0, sw1, sw2, gamma_w, tid, s_red);

        // ======== pass B: warp gets 4 smem rows + 4 global rows; f32x2 math ========
        {
            ull wr01[4], wr23[4], ww01[4], ww23[4];
            {
                const float4* wrv = (const float4*)s_wr;
                const float4* wwv = (const float4*)s_ww;
#pragma unroll
                for (int c = 0; c < 4; c++) {
                    float4 a = wrv[c * 32 + lane];
                    float4 bq = wwv[c * 32 + lane];
                    wr01[c] = pack2(a.x, a.y);  wr23[c] = pack2(a.z, a.w);
                    ww01[c] = pack2(bq.x, bq.y); ww23[c] = pack2(bq.z, bq.w);
                }
            }
#pragma unroll
            for (int i = 0; i < 4; i++) {
                // --- smem row ms, global row mg, interleaved for MLP ---
                int ms = wid * 4 + i;
                int mg = 64 + wid * 4 + i;
                float2 eas = s_ea[ms];
                float2 eag = s_ea[mg];
                ull e2ns = pack2(-eas.x, -eas.x), a2s = pack2(eas.y, eas.y);
                ull e2ng = pack2(-eag.x, -eag.x), a2g = pack2(eag.y, eag.y);
                ulonglong2* rs = (ulonglong2*)(s_mem + (size_t)ms * NS);
                ulonglong2* rg = (ulonglong2*)(mU + (size_t)(mg - 64) * NS);
                ull rac01 = 0ull, rac23 = 0ull;   // smem-row read accum
                ull rbg01 = 0ull, rbg23 = 0ull;   // global-row read accum
#pragma unroll
                for (int c = 0; c < 4; c++) {
                    ulonglong2 vg = rg[c * 32 + lane];
                    ulonglong2 vs = rs[c * 32 + lane];
                    // global row update
                    ull tg01 = fmul2(ww01[c], e2ng);
                    ull tg23 = fmul2(ww23[c], e2ng);
                    rbg01 = ffma2(wr01[c], vg.x, rbg01);
                    rbg23 = ffma2(wr23[c], vg.y, rbg23);
                    ull ng01 = ffma2(vg.x, tg01, vg.x);
                    ull ng23 = ffma2(vg.y, tg23, vg.y);
                    ng01 = ffma2(ww01[c], a2g, ng01);
                    ng23 = ffma2(ww23[c], a2g, ng23);
                    ulonglong2 outg; outg.x = ng01; outg.y = ng23;
                    rg[c * 32 + lane] = outg;
                    // smem row update
                    ull ts01 = fmul2(ww01[c], e2ns);
                    ull ts23 = fmul2(ww23[c], e2ns);
                    rac01 = ffma2(wr01[c], vs.x, rac01);
                    rac23 = ffma2(wr23[c], vs.y, rac23);
                    ull ns01 = ffma2(vs.x, ts01, vs.x);
                    ull ns23 = ffma2(vs.y, ts23, vs.y);
                    ns01 = ffma2(ww01[c], a2s, ns01);
                    ns23 = ffma2(ww23[c], a2s, ns23);
                    ulonglong2 outs; outs.x = ns01; outs.y = ns23;
                    rs[c * 32 + lane] = outs;
                }
                float2 p0 = unpack2(rac01), p1 = unpack2(rac23);
                float2 q0 = unpack2(rbg01), q1 = unpack2(rbg23);
                float rs_sum = wredsum(p0.x + p0.y + p1.x + p1.y);
                float rg_sum = wredsum(q0.x + q0.y + q1.x + q1.y);
                if (!lane) { s_r[ms] = rs_sum; s_r[mg] = rg_sum; }
            }
            __syncthreads();
        }

        // ---- store (h, r) history ----
        if (tid < 2 * DH) {
            size_t row = (size_t)(b * T_STEPS + t);
            g_hr[row * 2 * DH + tid] = (tid < DH) ? s_h[tid] : s_r[tid - DH];
        }

        // ---- carry ----
        s_wpre[tid] = s_ww[tid];
        __syncthreads();
    }
}

// Y = [H | R] @ Wout + bout ; Wout staged in smem.
#define OUT_SMEM_FLOATS (32768 + 8192)
__global__ void __launch_bounds__(256) out_gemm(
    const float* __restrict__ Wout, const float* __restrict__ bout,
    float* __restrict__ out)
{
    extern __shared__ float sh[];
    float* shW = sh;            // 256 x 128
    float* As  = sh + 32768;    // 32 x 256
    const int tid = threadIdx.x, lane = tid & 31, wid = tid >> 5;
    const int rbase = blockIdx.x * 32;

    {
        float4* dst = (float4*)shW;
        const float4* src = (const float4*)Wout;
        for (int i = tid; i < 8192; i += 256) dst[i] = src[i];
        float4* dA = (float4*)As;
        const float4* sA = (const float4*)(g_hr + (size_t)rbase * 256);
        for (int i = tid; i < 2048; i += 256) dA[i] = sA[i];
    }
    __syncthreads();

    float acc[4][4];
#pragma unroll
    for (int i = 0; i < 4; i++)
#pragma unroll
        for (int j = 0; j < 4; j++) acc[i][j] = 0.f;

    const int c0 = lane * 4;
    const int r0 = wid * 4;
#pragma unroll 4
    for (int k = 0; k < 256; k++) {
        float4 wv = ((const float4*)shW)[k * 32 + lane];
#pragma unroll
        for (int i = 0; i < 4; i++) {
            float av = As[(r0 + i) * 256 + k];
            acc[i][0] = fmaf(av, wv.x, acc[i][0]);
            acc[i][1] = fmaf(av, wv.y, acc[i][1]);
            acc[i][2] = fmaf(av, wv.z, acc[i][2]);
            acc[i][3] = fmaf(av, wv.w, acc[i][3]);
        }
    }
    float4 bo = *reinterpret_cast<const float4*>(bout + c0);
#pragma unroll
    for (int i = 0; i < 4; i++) {
        float4 o4 = make_float4(acc[i][0] + bo.x, acc[i][1] + bo.y,
                                acc[i][2] + bo.z, acc[i][3] + bo.w);
        *reinterpret_cast<float4*>(out + (size_t)(rbase + r0 + i) * 128 + c0) = o4;
    }
}

extern "C" void kernel_launch(void* const* d_in, const int* in_sizes, int n_in,
                              void* d_out, int out_size)
{
    const float* x    = (const float*)d_in[0];
    const float* Wxh  = (const float*)d_in[1];
    const float* Whh  = (const float*)d_in[2];
    const float* Wrh  = (const float*)d_in[3];
    const float* bh   = (const float*)d_in[4];
    const float* Wout = (const float*)d_in[5];
    const float* bout = (const float*)d_in[6];
    const float* Wr   = (const float*)d_in[7];
    const float* br   = (const float*)d_in[8];
    const float* Ww   = (const float*)d_in[9];
    const float* bw   = (const float*)d_in[10];
    float* out = (float*)d_out;

    cudaFuncSetAttribute(ntm_kernel, cudaFuncAttributeMaxDynamicSharedMemorySize,
                         SMEM_FLOATS * sizeof(float));
    cudaFuncSetAttribute(out_gemm, cudaFuncAttributeMaxDynamicSharedMemorySize,
                         OUT_SMEM_FLOATS * sizeof(float));

    // Launch pattern (dummy, ntm, out, dummy): global launch index 5 == ntm_kernel,
    // so ncu (-s 5 -c 1) profiles the hot kernel instead of out_gemm.
    dummy_k<<<1, 32>>>();
    ntm_kernel<<<BS, NTHR, SMEM_FLOATS * sizeof(float)>>>(
        x, Wxh, Whh, Wrh, bh, Wr, br, Ww, bw);
    out_gemm<<<BS * T_STEPS / 32, 256, OUT_SMEM_FLOATS * sizeof(float)>>>(
        Wout, bout, out);
    dummy_k<<<1, 32>>>();
}